// round 1
// baseline (speedup 1.0000x reference)
#include <cuda_runtime.h>
#include <math.h>

#define HW    1024
#define TILE  128
#define HALO  12
#define BUFW  152
#define BUFN  (152*152)
#define NT    1024
#define INFV  __int_as_float(0x7f800000)

// Deterministic per-tile partial sums: [z][img][tile][{sum_skel, sum_skel*other}]
__device__ float g_part[2*32*64*2];

__device__ __forceinline__ float sigmoidf_(float x){ return 1.0f/(1.0f+__expf(-x)); }
__device__ __forceinline__ float4 ld4s(const float* p){ return *reinterpret_cast<const float4*>(p); }

// Horizontal max3 of a guarded e-row, 4 outputs per lane, neighbors via shuffle.
__device__ __forceinline__ float4 hmax_row(const float* p, int lane){
    float4 v = ld4s(p);
    v.x = (v.x > 1.5f) ? -1.0f : v.x;
    v.y = (v.y > 1.5f) ? -1.0f : v.y;
    v.z = (v.z > 1.5f) ? -1.0f : v.z;
    v.w = (v.w > 1.5f) ? -1.0f : v.w;
    float lf = __shfl_up_sync(0xffffffffu, v.w, 1);
    float rf = __shfl_down_sync(0xffffffffu, v.x, 1);
    if (lane == 0)  { float t = p[-1]; lf = (t > 1.5f) ? -1.0f : t; }
    if (lane == 31) { float t = p[4];  rf = (t > 1.5f) ? -1.0f : t; }
    float4 w;
    w.x = fmaxf(lf,  fmaxf(v.x, v.y));
    w.y = fmaxf(v.x, fmaxf(v.y, v.z));
    w.z = fmaxf(v.y, fmaxf(v.z, v.w));
    w.w = fmaxf(v.z, fmaxf(v.w, rf));
    return w;
}

__global__ __launch_bounds__(NT, 1)
void cldice_main(const float* __restrict__ logits, const float* __restrict__ targets){
    extern __shared__ float sm[];
    float* A = sm;
    float* B = sm + BUFN;

    const int tid     = threadIdx.x;
    const int tileIdx = blockIdx.x;     // 0..63  (8x8 tiles of 128x128)
    const int img     = blockIdx.y;     // 0..31  (b*2 + c)
    const int z       = blockIdx.z;     // 0 = skel(pred), 1 = skel(gt)
    const int tr0 = (tileIdx >> 3) * TILE;
    const int tc0 = (tileIdx & 7)  * TILE;
    const int base_r = tr0 - HALO;
    const int base_c = tc0 - HALO;
    const size_t ioff = (size_t)img * (HW*HW);
    const float* src = (z == 0 ? logits : targets) + ioff;

    // ---- Load tile + halo into A (+INF outside image). ----
    for (int idx = tid; idx < BUFN; idx += NT){
        int r  = idx / BUFW;
        int c  = idx - r*BUFW;
        int gr = base_r + r, gc = base_c + c;
        float v = INFV;
        if ((unsigned)gr < (unsigned)HW && (unsigned)gc < (unsigned)HW){
            float x = src[(size_t)gr*HW + gc];
            v = (z == 0) ? sigmoidf_(x) : x;
        }
        A[idx] = v;
    }
    // B outer ring -> +INF (never written by erode; read only for discardable radii).
    if (tid < BUFW){
        B[tid]                   = INFV;
        B[(BUFW-1)*BUFW + tid]   = INFV;
        B[tid*BUFW]              = INFV;
        B[tid*BUFW + (BUFW-1)]   = INFV;
    }
    __syncthreads();

    // ---- erode mapping: 38 float4-cols x 25 groups of 6 rows = 950 threads ----
    const int  ef4 = tid % 38;
    const int  eg  = tid / 38;
    const bool eactive = (tid < 950);
    const int  ec0 = ef4 * 4;
    const int  er0 = 1 + eg * 6;
    const int  egc = base_c + ec0;
    const bool ck0 = (unsigned)(egc+0) < (unsigned)HW;
    const bool ck1 = (unsigned)(egc+1) < (unsigned)HW;
    const bool ck2 = (unsigned)(egc+2) < (unsigned)HW;
    const bool ck3 = (unsigned)(egc+3) < (unsigned)HW;

    // ---- dilate mapping: lane = f4-col (32 x 4 = 128 wide), warp-group = 4 rows ----
    const int lane = tid & 31;
    const int dg   = tid >> 5;
    const int cb   = HALO + lane*4;
    const int rb   = HALO + dg*4;

    float4 sk[4];
    sk[0] = make_float4(0.f,0.f,0.f,0.f); sk[1] = sk[0]; sk[2] = sk[0]; sk[3] = sk[0];

    #pragma unroll 1
    for (int t = 0; t < 10; t++){
        const float* IMG = (t & 1) ? B : A;
        float*       E   = (t & 1) ? A : B;

        // erode: E = 5-point min of IMG over full interior rows 1..150
        if (eactive){
            const int ro = (er0-1)*BUFW + ec0;
            float4 mA = ld4s(IMG + ro);
            float4 mB = ld4s(IMG + ro + BUFW);
            #pragma unroll
            for (int k = 0; k < 6; k++){
                const int rc = ro + (k+1)*BUFW;            // center row er0+k
                float4 mC = ld4s(IMG + rc + BUFW);
                float  l  = IMG[rc - 1];
                float  rt = IMG[rc + 4];
                float4 vm;
                vm.x = fminf(mA.x, fminf(mB.x, mC.x));
                vm.y = fminf(mA.y, fminf(mB.y, mC.y));
                vm.z = fminf(mA.z, fminf(mB.z, mC.z));
                vm.w = fminf(mA.w, fminf(mB.w, mC.w));
                float4 h;
                h.x = fminf(l,    fminf(mB.x, mB.y));
                h.y = fminf(mB.x, fminf(mB.y, mB.z));
                h.z = fminf(mB.y, fminf(mB.z, mB.w));
                h.w = fminf(mB.z, fminf(mB.w, rt));
                float4 e;
                e.x = fminf(vm.x, h.x);
                e.y = fminf(vm.y, h.y);
                e.z = fminf(vm.z, h.z);
                e.w = fminf(vm.w, h.w);
                const int  gr  = base_r + er0 + k;
                const bool rok = (unsigned)gr < (unsigned)HW;
                float4 o;
                o.x = (rok && ck0) ? e.x : INFV;
                o.y = (rok && ck1) ? e.y : INFV;
                o.z = (rok && ck2) ? e.z : INFV;
                o.w = (rok && ck3) ? e.w : INFV;
                *reinterpret_cast<float4*>(E + rc) = o;
                mA = mB; mB = mC;
            }
        }
        __syncthreads();

        // dilate(E) + skel accumulation (tile pixels only)
        {
            const float* Ep = E + (rb-1)*BUFW + cb;
            float4 w0 = hmax_row(Ep, lane);
            float4 w1 = hmax_row(Ep + BUFW, lane);
            #pragma unroll
            for (int k = 0; k < 4; k++){
                float4 w2 = hmax_row(Ep + (k+2)*BUFW, lane);
                float4 op;
                op.x = fmaxf(w0.x, fmaxf(w1.x, w2.x));
                op.y = fmaxf(w0.y, fmaxf(w1.y, w2.y));
                op.z = fmaxf(w0.z, fmaxf(w1.z, w2.z));
                op.w = fmaxf(w0.w, fmaxf(w1.w, w2.w));
                float4 im = ld4s(IMG + (rb+k)*BUFW + cb);
                sk[k].x += fmaxf(im.x - op.x, 0.0f);
                sk[k].y += fmaxf(im.y - op.y, 0.0f);
                sk[k].z += fmaxf(im.z - op.z, 0.0f);
                sk[k].w += fmaxf(im.w - op.w, 0.0f);
                w0 = w1; w1 = w2;
            }
        }
        __syncthreads();
    }

    // ---- fused reduction: acc0 = sum skel, acc1 = sum skel*other ----
    float acc0 = 0.f, acc1 = 0.f;
    {
        const int ggr = tr0 + dg*4;
        const int ggc = tc0 + lane*4;
        const float* obase = ((z == 0) ? targets : logits) + ioff;
        #pragma unroll
        for (int k = 0; k < 4; k++){
            float4 o = ld4s(obase + (size_t)(ggr+k)*HW + ggc);
            if (z == 1){
                o.x = sigmoidf_(o.x); o.y = sigmoidf_(o.y);
                o.z = sigmoidf_(o.z); o.w = sigmoidf_(o.w);
            }
            acc0 += sk[k].x + sk[k].y + sk[k].z + sk[k].w;
            acc1 += sk[k].x*o.x + sk[k].y*o.y + sk[k].z*o.z + sk[k].w*o.w;
        }
    }
    #pragma unroll
    for (int off = 16; off; off >>= 1){
        acc0 += __shfl_xor_sync(0xffffffffu, acc0, off);
        acc1 += __shfl_xor_sync(0xffffffffu, acc1, off);
    }
    if (lane == 0){ A[dg*2] = acc0; A[dg*2+1] = acc1; }
    __syncthreads();
    if (tid < 32){
        float a0 = A[tid*2], a1 = A[tid*2+1];
        #pragma unroll
        for (int off = 16; off; off >>= 1){
            a0 += __shfl_xor_sync(0xffffffffu, a0, off);
            a1 += __shfl_xor_sync(0xffffffffu, a1, off);
        }
        if (tid == 0){
            const int base = ((z*32 + img)*64 + tileIdx)*2;
            g_part[base + 0] = a0;
            g_part[base + 1] = a1;
        }
    }
}

__global__ void cldice_finalize(float* __restrict__ out){
    const int i = threadIdx.x;          // image index 0..31 (b*2 + c)
    __shared__ float sh[32];
    float S2 = 0.f, S1 = 0.f, S4 = 0.f, S3 = 0.f;
    for (int t = 0; t < 64; t++){
        const int b0 = ((0*32 + i)*64 + t)*2;
        const int b1 = ((1*32 + i)*64 + t)*2;
        S2 += g_part[b0 + 0];   // sum skel_pred
        S1 += g_part[b0 + 1];   // sum skel_pred * target
        S4 += g_part[b1 + 0];   // sum skel_gt
        S3 += g_part[b1 + 1];   // sum skel_gt * pred
    }
    const float eps = 1e-6f;
    const float tp = S1 / (S2 + eps);
    const float ts = S3 / (S4 + eps);
    const float cl = 2.0f*tp*ts / (tp + ts + eps);
    sh[i] = cl;
    __syncthreads();
    if (i == 0){
        float ca = 0.f, cv = 0.f;
        for (int b = 0; b < 16; b++){ ca += sh[2*b]; cv += sh[2*b + 1]; }
        out[0] = 1.0f - 0.5f*(ca*(1.0f/16.0f) + cv*(1.0f/16.0f));
    }
}

extern "C" void kernel_launch(void* const* d_in, const int* in_sizes, int n_in,
                              void* d_out, int out_size){
    const float* logits  = (const float*)d_in[0];
    const float* targets = (const float*)d_in[1];
    float* out = (float*)d_out;

    cudaFuncSetAttribute(cldice_main, cudaFuncAttributeMaxDynamicSharedMemorySize,
                         (int)(2*BUFN*sizeof(float)));

    dim3 grid(64, 32, 2);
    cldice_main<<<grid, NT, 2*BUFN*sizeof(float)>>>(logits, targets);
    cldice_finalize<<<1, 32>>>(out);
}

// round 3
// speedup vs baseline: 1.1945x; 1.1945x over previous
#include <cuda_runtime.h>
#include <math.h>

#define HW     1024
#define TILEH  128
#define TILEW  64
#define HALO   12
#define BUFH   152
#define BUFW   88
#define BUFN   (BUFH*BUFW)     // 13376 floats = 53.5 KB
#define NT     512
#define NTILES 128             // 8 row-tiles x 16 col-tiles
#define INFV   __int_as_float(0x7f800000)

// per-tile partials: [z][img][tile][{sum_skel, sum_skel*other}]
__device__ float g_part[2*32*NTILES*2];

__device__ __forceinline__ float sigmoidf_(float x){ return 1.0f/(1.0f+__expf(-x)); }
__device__ __forceinline__ float4 ld4s(const float* p){ return *reinterpret_cast<const float4*>(p); }

// Horizontal max3 of a guarded e-row; 4 outputs/lane; 16-lane row segments.
__device__ __forceinline__ float4 hmax_row16(const float* p, int ln16){
    float4 v = ld4s(p);
    v.x = (v.x > 1.5f) ? -1.0f : v.x;
    v.y = (v.y > 1.5f) ? -1.0f : v.y;
    v.z = (v.z > 1.5f) ? -1.0f : v.z;
    v.w = (v.w > 1.5f) ? -1.0f : v.w;
    float lf = __shfl_up_sync(0xffffffffu, v.w, 1, 16);
    float rf = __shfl_down_sync(0xffffffffu, v.x, 1, 16);
    if (ln16 == 0)  { float t = p[-1]; lf = (t > 1.5f) ? -1.0f : t; }
    if (ln16 == 15) { float t = p[4];  rf = (t > 1.5f) ? -1.0f : t; }
    float4 w;
    w.x = fmaxf(lf,  fmaxf(v.x, v.y));
    w.y = fmaxf(v.x, fmaxf(v.y, v.z));
    w.z = fmaxf(v.y, fmaxf(v.z, v.w));
    w.w = fmaxf(v.z, fmaxf(v.w, rf));
    return w;
}

__global__ __launch_bounds__(NT, 2)
void cldice_main(const float* __restrict__ logits, const float* __restrict__ targets){
    extern __shared__ float sm[];
    float* A = sm;
    float* B = sm + BUFN;

    const int tid     = threadIdx.x;
    const int tileIdx = blockIdx.x;            // 0..127
    const int img     = blockIdx.y;            // 0..31 (b*2+c)
    const int z       = blockIdx.z;            // 0: skel(pred), 1: skel(gt)
    const int tr0 = (tileIdx >> 4) * TILEH;    // 8 row tiles
    const int tc0 = (tileIdx & 15) * TILEW;    // 16 col tiles
    const int base_r = tr0 - HALO;
    const int base_c = tc0 - HALO;
    const size_t ioff = (size_t)img * (HW*HW);
    const float* src = (z == 0 ? logits : targets) + ioff;

    // ---- Load tile + halo 12 into A (+INF outside image) ----
    for (int idx = tid; idx < BUFN; idx += NT){
        int r  = idx / BUFW;
        int c  = idx - r*BUFW;
        int gr = base_r + r, gc = base_c + c;
        float v = INFV;
        if ((unsigned)gr < (unsigned)HW && (unsigned)gc < (unsigned)HW){
            float x = src[(size_t)gr*HW + gc];
            v = (z == 0) ? sigmoidf_(x) : x;
        }
        A[idx] = v;
    }
    __syncthreads();

    // ---- erode mapping: 22 float4-cols x 23 groups of 7 rows = 506 threads ----
    const int  ef4 = tid % 22;
    const int  eg  = tid / 22;
    const bool eactive = (tid < 506);
    const int  ec0 = ef4 * 4;
    const int  erow0 = 1 + eg * 7;             // first center row of this group
    const int  egc = base_c + ec0;
    const bool ck0 = (unsigned)(egc+0) < (unsigned)HW;
    const bool ck1 = (unsigned)(egc+1) < (unsigned)HW;
    const bool ck2 = (unsigned)(egc+2) < (unsigned)HW;
    const bool ck3 = (unsigned)(egc+3) < (unsigned)HW;

    // ---- dilate mapping: half-warp (16 lanes) owns 4 rows x 64 cols ----
    const int ln16 = tid & 15;
    const int hw16 = tid >> 4;                 // 0..31
    const int cb   = HALO + ln16*4;            // 12..72
    const int rb   = HALO + hw16*4;            // 12..136

    float4 sk[4];
    sk[0] = make_float4(0.f,0.f,0.f,0.f); sk[1] = sk[0]; sk[2] = sk[0]; sk[3] = sk[0];

    #pragma unroll 1
    for (int t = 0; t < 10; t++){
        const float* IMG = (t & 1) ? B : A;
        float*       E   = (t & 1) ? A : B;

        // erode over shrinking region rows/cols [1+t, 150-t]/[1+t, 86-t]
        if (eactive && (ec0+3 >= 1+t) && (ec0 <= 86-t)){
            int k0 = 1 + t - erow0;   if (k0 < 0) k0 = 0;
            int k1 = 150 - t - erow0; if (k1 > 6) k1 = 6;
            if (k0 <= k1){
                const int rbase = erow0 + k0;
                const float* P = IMG + (rbase-1)*BUFW + ec0;   // row above first center
                float4 mA = ld4s(P);
                float4 mB = ld4s(P + BUFW);
                for (int k = k0; k <= k1; k++){
                    const int off = (k - k0 + 1)*BUFW;          // center row offset from P
                    float4 mC = ld4s(P + off + BUFW);
                    float  l  = P[off - 1];
                    float  rt = P[off + 4];
                    float4 vm;
                    vm.x = fminf(mA.x, fminf(mB.x, mC.x));
                    vm.y = fminf(mA.y, fminf(mB.y, mC.y));
                    vm.z = fminf(mA.z, fminf(mB.z, mC.z));
                    vm.w = fminf(mA.w, fminf(mB.w, mC.w));
                    float4 h;
                    h.x = fminf(l,    fminf(mB.x, mB.y));
                    h.y = fminf(mB.x, fminf(mB.y, mB.z));
                    h.z = fminf(mB.y, fminf(mB.z, mB.w));
                    h.w = fminf(mB.z, fminf(mB.w, rt));
                    float4 e;
                    e.x = fminf(vm.x, h.x);
                    e.y = fminf(vm.y, h.y);
                    e.z = fminf(vm.z, h.z);
                    e.w = fminf(vm.w, h.w);
                    const int  gr  = base_r + rbase + (k - k0);
                    const bool rok = (unsigned)gr < (unsigned)HW;
                    float4 o;
                    o.x = (rok && ck0) ? e.x : INFV;
                    o.y = (rok && ck1) ? e.y : INFV;
                    o.z = (rok && ck2) ? e.z : INFV;
                    o.w = (rok && ck3) ? e.w : INFV;
                    *reinterpret_cast<float4*>(E + (rbase + (k-k0))*BUFW + ec0) = o;
                    mA = mB; mB = mC;
                }
            }
        }
        __syncthreads();

        // dilate(E) + skel accumulation over the 128x64 tile
        {
            const float* Ep = E + (rb-1)*BUFW + cb;
            float4 w0 = hmax_row16(Ep, ln16);
            float4 w1 = hmax_row16(Ep + BUFW, ln16);
            #pragma unroll
            for (int k = 0; k < 4; k++){
                float4 w2 = hmax_row16(Ep + (k+2)*BUFW, ln16);
                float4 op;
                op.x = fmaxf(w0.x, fmaxf(w1.x, w2.x));
                op.y = fmaxf(w0.y, fmaxf(w1.y, w2.y));
                op.z = fmaxf(w0.z, fmaxf(w1.z, w2.z));
                op.w = fmaxf(w0.w, fmaxf(w1.w, w2.w));
                float4 im = ld4s(IMG + (rb+k)*BUFW + cb);
                sk[k].x += fmaxf(im.x - op.x, 0.0f);
                sk[k].y += fmaxf(im.y - op.y, 0.0f);
                sk[k].z += fmaxf(im.z - op.z, 0.0f);
                sk[k].w += fmaxf(im.w - op.w, 0.0f);
                w0 = w1; w1 = w2;
            }
        }
        __syncthreads();
    }

    // ---- fused reduction: acc0 = sum skel, acc1 = sum skel*other ----
    float acc0 = 0.f, acc1 = 0.f;
    {
        const int ggr = tr0 + hw16*4;
        const int ggc = tc0 + ln16*4;
        const float* obase = ((z == 0) ? targets : logits) + ioff;
        #pragma unroll
        for (int k = 0; k < 4; k++){
            float4 o = ld4s(obase + (size_t)(ggr+k)*HW + ggc);
            if (z == 1){
                o.x = sigmoidf_(o.x); o.y = sigmoidf_(o.y);
                o.z = sigmoidf_(o.z); o.w = sigmoidf_(o.w);
            }
            acc0 += sk[k].x + sk[k].y + sk[k].z + sk[k].w;
            acc1 += sk[k].x*o.x + sk[k].y*o.y + sk[k].z*o.z + sk[k].w*o.w;
        }
    }
    #pragma unroll
    for (int off = 16; off; off >>= 1){
        acc0 += __shfl_xor_sync(0xffffffffu, acc0, off);
        acc1 += __shfl_xor_sync(0xffffffffu, acc1, off);
    }
    const int wid = tid >> 5;
    if ((tid & 31) == 0){ A[wid*2] = acc0; A[wid*2+1] = acc1; }
    __syncthreads();
    if (tid < 16){
        float a0 = A[tid*2], a1 = A[tid*2+1];
        #pragma unroll
        for (int off = 8; off; off >>= 1){
            a0 += __shfl_xor_sync(0x0000ffffu, a0, off, 16);
            a1 += __shfl_xor_sync(0x0000ffffu, a1, off, 16);
        }
        if (tid == 0){
            const int base = ((z*32 + img)*NTILES + tileIdx)*2;
            g_part[base + 0] = a0;
            g_part[base + 1] = a1;
        }
    }
}

__global__ void cldice_finalize(float* __restrict__ out){
    // 1024 threads: warp w = image w; lanes stride over 128 tiles.
    const int tid  = threadIdx.x;
    const int im   = tid >> 5;
    const int lane = tid & 31;
    __shared__ float sh[32];
    float S2 = 0.f, S1 = 0.f, S4 = 0.f, S3 = 0.f;
    #pragma unroll
    for (int t = lane; t < NTILES; t += 32){
        const int b0 = ((0*32 + im)*NTILES + t)*2;
        const int b1 = ((1*32 + im)*NTILES + t)*2;
        S2 += g_part[b0 + 0];
        S1 += g_part[b0 + 1];
        S4 += g_part[b1 + 0];
        S3 += g_part[b1 + 1];
    }
    #pragma unroll
    for (int off = 16; off; off >>= 1){
        S2 += __shfl_xor_sync(0xffffffffu, S2, off);
        S1 += __shfl_xor_sync(0xffffffffu, S1, off);
        S4 += __shfl_xor_sync(0xffffffffu, S4, off);
        S3 += __shfl_xor_sync(0xffffffffu, S3, off);
    }
    if (lane == 0){
        const float eps = 1e-6f;
        const float tp = S1 / (S2 + eps);
        const float ts = S3 / (S4 + eps);
        sh[im] = 2.0f*tp*ts / (tp + ts + eps);
    }
    __syncthreads();
    if (tid < 32){
        float c = sh[tid];
        #pragma unroll
        for (int off = 16; off; off >>= 1)
            c += __shfl_xor_sync(0xffffffffu, c, off);
        if (tid == 0)
            out[0] = 1.0f - c * (1.0f/32.0f);   // 0.5*(mean_a + mean_v) = sum/32
    }
}

extern "C" void kernel_launch(void* const* d_in, const int* in_sizes, int n_in,
                              void* d_out, int out_size){
    const float* logits  = (const float*)d_in[0];
    const float* targets = (const float*)d_in[1];
    float* out = (float*)d_out;

    cudaFuncSetAttribute(cldice_main, cudaFuncAttributeMaxDynamicSharedMemorySize,
                         (int)(2*BUFN*sizeof(float)));

    dim3 grid(NTILES, 32, 2);
    cldice_main<<<grid, NT, 2*BUFN*sizeof(float)>>>(logits, targets);
    cldice_finalize<<<1, 1024>>>(out);
}